// round 13
// baseline (speedup 1.0000x reference)
#include <cuda_runtime.h>
#include <cstdint>

#define D_MODEL 1024
#define N_HEADS 16
#define D_HEAD  64
#define BATCH   4
#define SEQ     2048
#define M_TOT   (BATCH * SEQ)   // 8192

// Scratch (device globals: allocation-free per harness rules)
__device__ float g_Q[(size_t)BATCH * N_HEADS * SEQ * D_HEAD];   // [b,h,s,dh]
__device__ float g_K[(size_t)BATCH * N_HEADS * SEQ * D_HEAD];
__device__ float g_V[(size_t)BATCH * N_HEADS * SEQ * D_HEAD];
__device__ float g_ctx[(size_t)M_TOT * D_MODEL];                // [b*s, d]

// ---------------------------------------------------------------------------
// tf32 helpers
// ---------------------------------------------------------------------------
__device__ __forceinline__ uint32_t f2tf32(float f) {
    uint32_t u;
    asm("cvt.rna.tf32.f32 %0, %1;" : "=r"(u) : "f"(f));
    return u;
}
__device__ __forceinline__ float f2tf32f(float f) {
    return __uint_as_float(f2tf32(f));
}
__device__ __forceinline__ float4 f2tf32f4(float4 v) {
    return make_float4(f2tf32f(v.x), f2tf32f(v.y), f2tf32f(v.z), f2tf32f(v.w));
}

__device__ __forceinline__ void mma_tf32_16x8x8(
    float c[4], const uint32_t a[4], const uint32_t b[2])
{
    asm volatile(
        "mma.sync.aligned.m16n8k8.row.col.f32.tf32.tf32.f32 "
        "{%0,%1,%2,%3}, {%4,%5,%6,%7}, {%8,%9}, {%0,%1,%2,%3};"
        : "+f"(c[0]), "+f"(c[1]), "+f"(c[2]), "+f"(c[3])
        : "r"(a[0]), "r"(a[1]), "r"(a[2]), "r"(a[3]),
          "r"(b[0]), "r"(b[1]));
}

// ---------------------------------------------------------------------------
// tf32 tensor-core GEMM core v3: C_tile(128x128) = A(128xK) * W(Kx128), K=1024.
// 128 threads = 4 warps in 2(M) x 2(N); each warp computes a 64x64 tile via
// 4x8 m16n8k8 fragments (32 MMA per k8 on 32 LDS -> 1.0 LDS/MMA).
// R6-validated smem layout (A stride 20, B stride 136, conflict-free fragment
// reads), tf32 pre-converted at staging, double-buffered with one sync per
// k-tile and register prefetch of the next tile.
// ---------------------------------------------------------------------------
__device__ __forceinline__ void gemm_tf32_core(
    const float* __restrict__ A,   // [M, 1024] row-major
    const float* __restrict__ W,   // [1024, 1024] row-major
    float acc[4][8][4], int bm, int bn)
{
    __shared__ __align__(16) float As[2][128][20];   // [m][k], tf32 bits
    __shared__ __align__(16) float Bs[2][16][136];   // [k][n], tf32 bits

    const int tid  = threadIdx.x;    // 0..127
    const int warp = tid >> 5;
    const int lane = tid & 31;
    const int g    = lane >> 2;      // 0..7
    const int t    = lane & 3;       // 0..3
    const int m_warp = (warp & 1) * 64;
    const int n_warp = (warp >> 1) * 64;

    // staging: A -> thread owns one row (all 16 k); B -> row tid>>3, 16 cols
    const float* Arow = A + (size_t)(bm + tid) * 1024;
    const int brow = tid >> 3;              // 0..15
    const int bcol = (tid & 7) * 16;        // 0..112
    const float* Bbase = W + (size_t)brow * 1024 + bn + bcol;

    float4 pa[4], pb[4];
    #pragma unroll
    for (int i = 0; i < 4; i++) {
        pa[i] = *reinterpret_cast<const float4*>(Arow + i * 4);
        pb[i] = *reinterpret_cast<const float4*>(Bbase + i * 4);
    }

    // stash prefetched regs into smem buffer (tf32-converted)
    #pragma unroll
    for (int i = 0; i < 4; i++) {
        *reinterpret_cast<float4*>(&As[0][tid][i * 4])         = f2tf32f4(pa[i]);
        *reinterpret_cast<float4*>(&Bs[0][brow][bcol + i * 4]) = f2tf32f4(pb[i]);
    }
    __syncthreads();

    for (int k0 = 0; k0 < 1024; k0 += 16) {
        const int cur = (k0 >> 4) & 1;

        // prefetch next k-tile into registers (overlaps MMA below)
        if (k0 + 16 < 1024) {
            const int kn = k0 + 16;
            #pragma unroll
            for (int i = 0; i < 4; i++) {
                pa[i] = *reinterpret_cast<const float4*>(Arow + kn + i * 4);
                pb[i] = *reinterpret_cast<const float4*>(
                    Bbase + (size_t)kn * 1024 + i * 4);
            }
        }

        // ---- MMA: 2 k8 steps from buffer `cur` ----
        #pragma unroll
        for (int s = 0; s < 2; s++) {
            const int ks = s * 8;
            uint32_t afr[4][4];
            #pragma unroll
            for (int i = 0; i < 4; i++) {
                int r = m_warp + i * 16 + g;
                afr[i][0] = __float_as_uint(As[cur][r    ][ks + t    ]);
                afr[i][1] = __float_as_uint(As[cur][r + 8][ks + t    ]);
                afr[i][2] = __float_as_uint(As[cur][r    ][ks + t + 4]);
                afr[i][3] = __float_as_uint(As[cur][r + 8][ks + t + 4]);
            }
            uint32_t bfr[8][2];
            #pragma unroll
            for (int j = 0; j < 8; j++) {
                int c = n_warp + j * 8 + g;
                bfr[j][0] = __float_as_uint(Bs[cur][ks + t    ][c]);
                bfr[j][1] = __float_as_uint(Bs[cur][ks + t + 4][c]);
            }
            #pragma unroll
            for (int i = 0; i < 4; i++)
                #pragma unroll
                for (int j = 0; j < 8; j++)
                    mma_tf32_16x8x8(acc[i][j], afr[i], bfr[j]);
        }

        // ---- stash next tile into the other buffer ----
        if (k0 + 16 < 1024) {
            const int nxt = cur ^ 1;
            #pragma unroll
            for (int i = 0; i < 4; i++) {
                *reinterpret_cast<float4*>(&As[nxt][tid][i * 4])         = f2tf32f4(pa[i]);
                *reinterpret_cast<float4*>(&Bs[nxt][brow][bcol + i * 4]) = f2tf32f4(pb[i]);
            }
            __syncthreads();
        }
    }
}

// ---------------------------------------------------------------------------
// QKV projection: out = x @ W_{q,k,v} + b, written in [b,h,s,dh] layout.
// grid = (M/128, N/128, 3), block = 128.
// ---------------------------------------------------------------------------
__global__ __launch_bounds__(128, 2)
void qkv_gemm_kernel(const float* __restrict__ x,
                     const float* __restrict__ Wq, const float* __restrict__ bq,
                     const float* __restrict__ Wk, const float* __restrict__ bk,
                     const float* __restrict__ Wv, const float* __restrict__ bv)
{
    const float* W; const float* bias; float* out;
    if      (blockIdx.z == 0) { W = Wq; bias = bq; out = g_Q; }
    else if (blockIdx.z == 1) { W = Wk; bias = bk; out = g_K; }
    else                      { W = Wv; bias = bv; out = g_V; }

    const int bm = blockIdx.x * 128;
    const int bn = blockIdx.y * 128;

    float acc[4][8][4];
    #pragma unroll
    for (int i = 0; i < 4; i++)
        #pragma unroll
        for (int j = 0; j < 8; j++)
            #pragma unroll
            for (int r = 0; r < 4; r++) acc[i][j][r] = 0.f;

    gemm_tf32_core(x, W, acc, bm, bn);

    const int warp = threadIdx.x >> 5;
    const int lane = threadIdx.x & 31;
    const int g    = lane >> 2;
    const int t    = lane & 3;
    const int m_warp = (warp & 1) * 64;
    const int n_warp = (warp >> 1) * 64;

    #pragma unroll
    for (int i = 0; i < 4; i++) {
        #pragma unroll
        for (int j = 0; j < 8; j++) {
            int n0 = bn + n_warp + j * 8 + t * 2;
            int h  = n0 >> 6;
            int dh = n0 & 63;
            float b0v = bias[n0], b1v = bias[n0 + 1];
            #pragma unroll
            for (int rr = 0; rr < 2; rr++) {
                int m = bm + m_warp + i * 16 + g + rr * 8;
                int b = m >> 11;
                int s = m & (SEQ - 1);
                float* dst = &out[(((size_t)(b * N_HEADS + h) * SEQ + s) * D_HEAD) + dh];
                float2 v = make_float2(acc[i][j][rr * 2] + b0v,
                                       acc[i][j][rr * 2 + 1] + b1v);
                *reinterpret_cast<float2*>(dst) = v;
            }
        }
    }
}

// ---------------------------------------------------------------------------
// Output projection: out = ctx @ W_o + b_o   (row-major [M, D])
// ---------------------------------------------------------------------------
__global__ __launch_bounds__(128, 2)
void out_gemm_kernel(const float* __restrict__ Wo,
                     const float* __restrict__ bo,
                     float* __restrict__ out)
{
    const int bm = blockIdx.x * 128;
    const int bn = blockIdx.y * 128;

    float acc[4][8][4];
    #pragma unroll
    for (int i = 0; i < 4; i++)
        #pragma unroll
        for (int j = 0; j < 8; j++)
            #pragma unroll
            for (int r = 0; r < 4; r++) acc[i][j][r] = 0.f;

    gemm_tf32_core(g_ctx, Wo, acc, bm, bn);

    const int warp = threadIdx.x >> 5;
    const int lane = threadIdx.x & 31;
    const int g    = lane >> 2;
    const int t    = lane & 3;
    const int m_warp = (warp & 1) * 64;
    const int n_warp = (warp >> 1) * 64;

    #pragma unroll
    for (int i = 0; i < 4; i++) {
        #pragma unroll
        for (int j = 0; j < 8; j++) {
            int n0 = bn + n_warp + j * 8 + t * 2;
            float b0v = bo[n0], b1v = bo[n0 + 1];
            #pragma unroll
            for (int rr = 0; rr < 2; rr++) {
                int m = bm + m_warp + i * 16 + g + rr * 8;
                float2 v = make_float2(acc[i][j][rr * 2] + b0v,
                                       acc[i][j][rr * 2 + 1] + b1v);
                *reinterpret_cast<float2*>(&out[(size_t)m * D_MODEL + n0]) = v;
            }
        }
    }
}

// ---------------------------------------------------------------------------
// Causal flash attention with tf32 tensor cores (unchanged from R6 — validated).
// ---------------------------------------------------------------------------
__global__ __launch_bounds__(128, 4)
void flash_attn_tc_kernel()
{
    __shared__ __align__(16) float Qs[64][68];
    __shared__ __align__(16) float Ks[32][68];
    __shared__ __align__(16) float Vs[32][72];
    __shared__ __align__(16) float Ps[64][36];

    const int tid  = threadIdx.x;
    const int warp = tid >> 5;
    const int lane = tid & 31;
    const int gID  = lane >> 2;
    const int tID  = lane & 3;
    const int qt   = blockIdx.x;
    const int bh   = blockIdx.y;
    const int qbase = qt << 6;
    const int r0   = warp << 4;

    const float sc = 0.125f * 1.44269504088896340736f;

    {
        const float* qsrc = &g_Q[((size_t)bh * SEQ + qbase) * D_HEAD];
        int row  = tid >> 1;
        int colb = (tid & 1) * 32;
        #pragma unroll
        for (int i = 0; i < 8; i++) {
            float4 v = *reinterpret_cast<const float4*>(
                &qsrc[(size_t)row * 64 + colb + i * 4]);
            Qs[row][colb + i*4 + 0] = f2tf32f(v.x * sc);
            Qs[row][colb + i*4 + 1] = f2tf32f(v.y * sc);
            Qs[row][colb + i*4 + 2] = f2tf32f(v.z * sc);
            Qs[row][colb + i*4 + 3] = f2tf32f(v.w * sc);
        }
    }

    float m0 = -1e30f, m1 = -1e30f, l0 = 0.f, l1 = 0.f;
    float co[8][4];
    #pragma unroll
    for (int j = 0; j < 8; j++)
        #pragma unroll
        for (int r = 0; r < 4; r++) co[j][r] = 0.f;

    const float* Kb = &g_K[(size_t)bh * SEQ * D_HEAD];
    const float* Vb = &g_V[(size_t)bh * SEQ * D_HEAD];

    __syncthreads();

    const int ntiles = 2 * qt + 2;
    for (int t = 0; t < ntiles; t++) {
        {
            int row  = tid >> 2;
            int colb = (tid & 3) * 16;
            const float* ks = Kb + ((size_t)t * 32 + row) * 64 + colb;
            const float* vs = Vb + ((size_t)t * 32 + row) * 64 + colb;
            #pragma unroll
            for (int i = 0; i < 4; i++) {
                float4 kv = *reinterpret_cast<const float4*>(&ks[i * 4]);
                Ks[row][colb + i*4 + 0] = f2tf32f(kv.x);
                Ks[row][colb + i*4 + 1] = f2tf32f(kv.y);
                Ks[row][colb + i*4 + 2] = f2tf32f(kv.z);
                Ks[row][colb + i*4 + 3] = f2tf32f(kv.w);
                float4 vv = *reinterpret_cast<const float4*>(&vs[i * 4]);
                Vs[row][colb + i*4 + 0] = f2tf32f(vv.x);
                Vs[row][colb + i*4 + 1] = f2tf32f(vv.y);
                Vs[row][colb + i*4 + 2] = f2tf32f(vv.z);
                Vs[row][colb + i*4 + 3] = f2tf32f(vv.w);
            }
        }
        __syncthreads();

        float sfrag[4][4];
        #pragma unroll
        for (int j = 0; j < 4; j++)
            #pragma unroll
            for (int r = 0; r < 4; r++) sfrag[j][r] = 0.f;

        #pragma unroll
        for (int k8 = 0; k8 < 64; k8 += 8) {
            uint32_t a[4];
            a[0] = __float_as_uint(Qs[r0 + gID    ][k8 + tID    ]);
            a[1] = __float_as_uint(Qs[r0 + gID + 8][k8 + tID    ]);
            a[2] = __float_as_uint(Qs[r0 + gID    ][k8 + tID + 4]);
            a[3] = __float_as_uint(Qs[r0 + gID + 8][k8 + tID + 4]);
            #pragma unroll
            for (int j = 0; j < 4; j++) {
                uint32_t b[2];
                b[0] = __float_as_uint(Ks[j*8 + gID][k8 + tID    ]);
                b[1] = __float_as_uint(Ks[j*8 + gID][k8 + tID + 4]);
                mma_tf32_16x8x8(sfrag[j], a, b);
            }
        }

        const int rg0 = qbase + r0 + gID;
        const int rg1 = rg0 + 8;
        if (t >= 2 * qt) {
            #pragma unroll
            for (int j = 0; j < 4; j++) {
                int key = t * 32 + j * 8 + tID * 2;
                if (key     > rg0) sfrag[j][0] = -1e30f;
                if (key + 1 > rg0) sfrag[j][1] = -1e30f;
                if (key     > rg1) sfrag[j][2] = -1e30f;
                if (key + 1 > rg1) sfrag[j][3] = -1e30f;
            }
        }

        float tm0 = -1e30f, tm1 = -1e30f;
        #pragma unroll
        for (int j = 0; j < 4; j++) {
            tm0 = fmaxf(tm0, fmaxf(sfrag[j][0], sfrag[j][1]));
            tm1 = fmaxf(tm1, fmaxf(sfrag[j][2], sfrag[j][3]));
        }
        tm0 = fmaxf(tm0, __shfl_xor_sync(0xffffffffu, tm0, 1));
        tm0 = fmaxf(tm0, __shfl_xor_sync(0xffffffffu, tm0, 2));
        tm1 = fmaxf(tm1, __shfl_xor_sync(0xffffffffu, tm1, 1));
        tm1 = fmaxf(tm1, __shfl_xor_sync(0xffffffffu, tm1, 2));

        float mn0 = fmaxf(m0, tm0), mn1 = fmaxf(m1, tm1);
        float al0 = exp2f(m0 - mn0), al1 = exp2f(m1 - mn1);
        m0 = mn0; m1 = mn1;

        float ls0 = 0.f, ls1 = 0.f;
        #pragma unroll
        for (int j = 0; j < 4; j++) {
            float p0 = f2tf32f(exp2f(sfrag[j][0] - m0));
            float p1 = f2tf32f(exp2f(sfrag[j][1] - m0));
            float p2 = f2tf32f(exp2f(sfrag[j][2] - m1));
            float p3 = f2tf32f(exp2f(sfrag[j][3] - m1));
            ls0 += p0 + p1;
            ls1 += p2 + p3;
            int col = j * 8 + tID * 2;
            *reinterpret_cast<float2*>(&Ps[r0 + gID    ][col]) = make_float2(p0, p1);
            *reinterpret_cast<float2*>(&Ps[r0 + gID + 8][col]) = make_float2(p2, p3);
        }
        ls0 += __shfl_xor_sync(0xffffffffu, ls0, 1);
        ls0 += __shfl_xor_sync(0xffffffffu, ls0, 2);
        ls1 += __shfl_xor_sync(0xffffffffu, ls1, 1);
        ls1 += __shfl_xor_sync(0xffffffffu, ls1, 2);
        l0 = l0 * al0 + ls0;
        l1 = l1 * al1 + ls1;

        #pragma unroll
        for (int j = 0; j < 8; j++) {
            co[j][0] *= al0; co[j][1] *= al0;
            co[j][2] *= al1; co[j][3] *= al1;
        }

        __syncwarp();

        #pragma unroll
        for (int k8 = 0; k8 < 32; k8 += 8) {
            uint32_t a[4];
            a[0] = __float_as_uint(Ps[r0 + gID    ][k8 + tID    ]);
            a[1] = __float_as_uint(Ps[r0 + gID + 8][k8 + tID    ]);
            a[2] = __float_as_uint(Ps[r0 + gID    ][k8 + tID + 4]);
            a[3] = __float_as_uint(Ps[r0 + gID + 8][k8 + tID + 4]);
            #pragma unroll
            for (int jn = 0; jn < 8; jn++) {
                uint32_t b[2];
                b[0] = __float_as_uint(Vs[k8 + tID    ][jn*8 + gID]);
                b[1] = __float_as_uint(Vs[k8 + tID + 4][jn*8 + gID]);
                mma_tf32_16x8x8(co[jn], a, b);
            }
        }
        __syncthreads();
    }

    const float inv0 = 1.f / l0;
    const float inv1 = 1.f / l1;
    const int b = bh >> 4;
    const int h = bh & 15;
    const int grow0 = qbase + r0 + gID;
    const int grow1 = grow0 + 8;
    #pragma unroll
    for (int jn = 0; jn < 8; jn++) {
        int col = h * 64 + jn * 8 + tID * 2;
        *reinterpret_cast<float2*>(&g_ctx[(size_t)(b * SEQ + grow0) * D_MODEL + col]) =
            make_float2(co[jn][0] * inv0, co[jn][1] * inv0);
        *reinterpret_cast<float2*>(&g_ctx[(size_t)(b * SEQ + grow1) * D_MODEL + col]) =
            make_float2(co[jn][2] * inv1, co[jn][3] * inv1);
    }
}

// ---------------------------------------------------------------------------
extern "C" void kernel_launch(void* const* d_in, const int* in_sizes, int n_in,
                              void* d_out, int out_size)
{
    const float* x   = (const float*)d_in[0];
    const float* W_q = (const float*)d_in[1];
    const float* b_q = (const float*)d_in[2];
    const float* W_k = (const float*)d_in[3];
    const float* b_k = (const float*)d_in[4];
    const float* W_v = (const float*)d_in[5];
    const float* b_v = (const float*)d_in[6];
    const float* W_o = (const float*)d_in[7];
    const float* b_o = (const float*)d_in[8];
    float* out = (float*)d_out;

    dim3 gProj(M_TOT / 128, D_MODEL / 128, 3);
    qkv_gemm_kernel<<<gProj, 128>>>(x, W_q, b_q, W_k, b_k, W_v, b_v);

    dim3 gAttn(SEQ / 64, BATCH * N_HEADS);
    flash_attn_tc_kernel<<<gAttn, 128>>>();

    dim3 gOut(M_TOT / 128, D_MODEL / 128);
    out_gemm_kernel<<<gOut, 128>>>(W_o, b_o, out);
}

// round 15
// speedup vs baseline: 1.2044x; 1.2044x over previous
#include <cuda_runtime.h>
#include <cstdint>

#define D_MODEL 1024
#define N_HEADS 16
#define D_HEAD  64
#define BATCH   4
#define SEQ     2048
#define M_TOT   (BATCH * SEQ)   // 8192

// Scratch (device globals: allocation-free per harness rules)
__device__ float g_Q[(size_t)BATCH * N_HEADS * SEQ * D_HEAD];   // [b,h,s,dh]
__device__ float g_K[(size_t)BATCH * N_HEADS * SEQ * D_HEAD];
__device__ float g_V[(size_t)BATCH * N_HEADS * SEQ * D_HEAD];
__device__ float g_ctx[(size_t)M_TOT * D_MODEL];                // [b*s, d]

// ---------------------------------------------------------------------------
// tf32 helpers
// ---------------------------------------------------------------------------
__device__ __forceinline__ uint32_t f2tf32(float f) {
    uint32_t u;
    asm("cvt.rna.tf32.f32 %0, %1;" : "=r"(u) : "f"(f));
    return u;
}
__device__ __forceinline__ float f2tf32f(float f) {
    return __uint_as_float(f2tf32(f));
}
__device__ __forceinline__ float4 f2tf32f4(float4 v) {
    return make_float4(f2tf32f(v.x), f2tf32f(v.y), f2tf32f(v.z), f2tf32f(v.w));
}

__device__ __forceinline__ void mma_tf32_16x8x8(
    float c[4], const uint32_t a[4], const uint32_t b[2])
{
    asm volatile(
        "mma.sync.aligned.m16n8k8.row.col.f32.tf32.tf32.f32 "
        "{%0,%1,%2,%3}, {%4,%5,%6,%7}, {%8,%9}, {%0,%1,%2,%3};"
        : "+f"(c[0]), "+f"(c[1]), "+f"(c[2]), "+f"(c[3])
        : "r"(a[0]), "r"(a[1]), "r"(a[2]), "r"(a[3]),
          "r"(b[0]), "r"(b[1]));
}

__device__ __forceinline__ uint32_t smem_u32(const void* p) {
    return (uint32_t)__cvta_generic_to_shared(p);
}

#define CP16(dst_u32, src_ptr) \
    asm volatile("cp.async.cg.shared.global [%0], [%1], 16;" \
                 :: "r"(dst_u32), "l"(src_ptr) : "memory")

// ---------------------------------------------------------------------------
// tf32 tensor-core GEMM core v4: C_tile(128x128) = A(128xK) * W(Kx128), K=1024.
// R6-validated shape: 256 threads = 8 warps in 2(M) x 4(N), warp tile 64x32
// (4x4 m16n8k8), A stride 20 / B stride 136 (conflict-free fragment reads),
// cvt-at-read (bit-identical to R6). New: cp.async double-buffered staging —
// GMEM->SMEM with no register cost, one __syncthreads per k-tile, LDG latency
// overlapped with MMA of the previous tile.
//
// Hazard proof (single sync): at iter i, cp.async targets buf (i+1)&1, which
// was last READ by MMA at iter i-1. The wait+__syncthreads at the top of iter
// i happens after every warp's iter-(i-1) MMA in program order, so all reads
// of that buffer are complete before any thread issues the overwrite.
// ---------------------------------------------------------------------------
__device__ __forceinline__ void gemm_tf32_core(
    const float* __restrict__ A,   // [M, 1024] row-major
    const float* __restrict__ W,   // [1024, 1024] row-major
    float acc[4][4][4], int bm, int bn)
{
    __shared__ __align__(16) float As[2][128][20];   // [m][k]
    __shared__ __align__(16) float Bs[2][16][136];   // [k][n]

    const int tid  = threadIdx.x;
    const int warp = tid >> 5;
    const int lane = tid & 31;
    const int gID  = lane >> 2;     // 0..7
    const int tID  = lane & 3;      // 0..3
    const int m_warp = (warp & 1) * 64;
    const int n_warp = (warp >> 1) * 32;

    // staging slots: 2 x 16B per thread for A, 2 x 16B for B (512 each total)
    const int f0 = tid * 2, f1 = f0 + 1;
    const int ar0 = f0 >> 2, ak0 = (f0 & 3) << 2;
    const int ar1 = f1 >> 2, ak1 = (f1 & 3) << 2;
    const int br0 = f0 >> 5, bc0 = (f0 & 31) << 2;
    const int br1 = f1 >> 5, bc1 = (f1 & 31) << 2;

    const float* a0 = A + (size_t)(bm + ar0) * 1024 + ak0;
    const float* a1 = A + (size_t)(bm + ar1) * 1024 + ak1;
    const float* b0 = W + (size_t)br0 * 1024 + bn + bc0;
    const float* b1 = W + (size_t)br1 * 1024 + bn + bc1;

    const uint32_t sa0 = smem_u32(&As[0][ar0][ak0]);
    const uint32_t sa1 = smem_u32(&As[0][ar1][ak1]);
    const uint32_t sb0 = smem_u32(&Bs[0][br0][bc0]);
    const uint32_t sb1 = smem_u32(&Bs[0][br1][bc1]);
    const uint32_t aoff = 128 * 20 * 4;   // bytes per A buffer
    const uint32_t boff = 16 * 136 * 4;   // bytes per B buffer

    // prologue: stage k-tile 0 into buffer 0
    CP16(sa0, a0);
    CP16(sa1, a1);
    CP16(sb0, b0);
    CP16(sb1, b1);
    asm volatile("cp.async.commit_group;" ::: "memory");

    for (int it = 0; it < 64; it++) {
        const int cur = it & 1;

        asm volatile("cp.async.wait_group 0;" ::: "memory");
        __syncthreads();

        // issue next tile's async copies (overlap with MMA below)
        if (it + 1 < 64) {
            const uint32_t nb = (uint32_t)(cur ^ 1);
            const int kn = (it + 1) * 16;
            CP16(sa0 + nb * aoff, a0 + kn);
            CP16(sa1 + nb * aoff, a1 + kn);
            CP16(sb0 + nb * boff, b0 + (size_t)kn * 1024);
            CP16(sb1 + nb * boff, b1 + (size_t)kn * 1024);
            asm volatile("cp.async.commit_group;" ::: "memory");
        }

        // ---- MMA: 2 k8 steps from buffer `cur` (cvt at read, as R6) ----
        #pragma unroll
        for (int s = 0; s < 2; s++) {
            const int ks = s * 8;
            uint32_t afrag[4][4];
            #pragma unroll
            for (int i = 0; i < 4; i++) {
                int r = m_warp + i * 16 + gID;
                afrag[i][0] = f2tf32(As[cur][r    ][ks + tID    ]);
                afrag[i][1] = f2tf32(As[cur][r + 8][ks + tID    ]);
                afrag[i][2] = f2tf32(As[cur][r    ][ks + tID + 4]);
                afrag[i][3] = f2tf32(As[cur][r + 8][ks + tID + 4]);
            }
            uint32_t bfrag[4][2];
            #pragma unroll
            for (int j = 0; j < 4; j++) {
                int c = n_warp + j * 8 + gID;
                bfrag[j][0] = f2tf32(Bs[cur][ks + tID    ][c]);
                bfrag[j][1] = f2tf32(Bs[cur][ks + tID + 4][c]);
            }
            #pragma unroll
            for (int i = 0; i < 4; i++)
                #pragma unroll
                for (int j = 0; j < 4; j++)
                    mma_tf32_16x8x8(acc[i][j], afrag[i], bfrag[j]);
        }
    }
}

// ---------------------------------------------------------------------------
// QKV projection: out = x @ W_{q,k,v} + b, written in [b,h,s,dh] layout.
// grid = (M/128, N/128, 3), z selects Q/K/V.
// ---------------------------------------------------------------------------
__global__ __launch_bounds__(256, 2)
void qkv_gemm_kernel(const float* __restrict__ x,
                     const float* __restrict__ Wq, const float* __restrict__ bq,
                     const float* __restrict__ Wk, const float* __restrict__ bk,
                     const float* __restrict__ Wv, const float* __restrict__ bv)
{
    const float* W; const float* bias; float* out;
    if      (blockIdx.z == 0) { W = Wq; bias = bq; out = g_Q; }
    else if (blockIdx.z == 1) { W = Wk; bias = bk; out = g_K; }
    else                      { W = Wv; bias = bv; out = g_V; }

    const int bm = blockIdx.x * 128;
    const int bn = blockIdx.y * 128;

    float acc[4][4][4];
    #pragma unroll
    for (int i = 0; i < 4; i++)
        #pragma unroll
        for (int j = 0; j < 4; j++)
            #pragma unroll
            for (int r = 0; r < 4; r++) acc[i][j][r] = 0.f;

    gemm_tf32_core(x, W, acc, bm, bn);

    const int warp   = threadIdx.x >> 5;
    const int lane   = threadIdx.x & 31;
    const int gID    = lane >> 2;
    const int tID    = lane & 3;
    const int m_warp = (warp & 1) * 64;
    const int n_warp = (warp >> 1) * 32;

    #pragma unroll
    for (int i = 0; i < 4; i++) {
        #pragma unroll
        for (int j = 0; j < 4; j++) {
            int n0 = bn + n_warp + j * 8 + tID * 2;
            int h  = n0 >> 6;
            int dh = n0 & 63;
            float b0v = bias[n0], b1v = bias[n0 + 1];
            #pragma unroll
            for (int rr = 0; rr < 2; rr++) {
                int m = bm + m_warp + i * 16 + gID + rr * 8;
                int b = m >> 11;
                int s = m & (SEQ - 1);
                float* dst = &out[(((size_t)(b * N_HEADS + h) * SEQ + s) * D_HEAD) + dh];
                float2 v = make_float2(acc[i][j][rr * 2] + b0v,
                                       acc[i][j][rr * 2 + 1] + b1v);
                *reinterpret_cast<float2*>(dst) = v;
            }
        }
    }
}

// ---------------------------------------------------------------------------
// Output projection: out = ctx @ W_o + b_o   (row-major [M, D])
// ---------------------------------------------------------------------------
__global__ __launch_bounds__(256, 2)
void out_gemm_kernel(const float* __restrict__ Wo,
                     const float* __restrict__ bo,
                     float* __restrict__ out)
{
    const int bm = blockIdx.x * 128;
    const int bn = blockIdx.y * 128;

    float acc[4][4][4];
    #pragma unroll
    for (int i = 0; i < 4; i++)
        #pragma unroll
        for (int j = 0; j < 4; j++)
            #pragma unroll
            for (int r = 0; r < 4; r++) acc[i][j][r] = 0.f;

    gemm_tf32_core(g_ctx, Wo, acc, bm, bn);

    const int warp   = threadIdx.x >> 5;
    const int lane   = threadIdx.x & 31;
    const int gID    = lane >> 2;
    const int tID    = lane & 3;
    const int m_warp = (warp & 1) * 64;
    const int n_warp = (warp >> 1) * 32;

    #pragma unroll
    for (int i = 0; i < 4; i++) {
        #pragma unroll
        for (int j = 0; j < 4; j++) {
            int n0 = bn + n_warp + j * 8 + tID * 2;
            float b0v = bo[n0], b1v = bo[n0 + 1];
            #pragma unroll
            for (int rr = 0; rr < 2; rr++) {
                int m = bm + m_warp + i * 16 + gID + rr * 8;
                float2 v = make_float2(acc[i][j][rr * 2] + b0v,
                                       acc[i][j][rr * 2 + 1] + b1v);
                *reinterpret_cast<float2*>(&out[(size_t)m * D_MODEL + n0]) = v;
            }
        }
    }
}

// ---------------------------------------------------------------------------
// Causal flash attention with tf32 tensor cores (R6-validated structure).
// New vs R6: next K/V tile prefetched into registers before the compute phase
// (hides LDG behind QK/softmax/PV), and staging stores are float4 (8 STS.128
// per thread per tile instead of 32 scalar STS).
// Block = 128 threads / 4 warps; Q tile 64 rows; KV tiles of 32 keys.
// grid = (SEQ/64, BATCH*N_HEADS)
// ---------------------------------------------------------------------------
__global__ __launch_bounds__(128, 4)
void flash_attn_tc_kernel()
{
    __shared__ __align__(16) float Qs[64][68];
    __shared__ __align__(16) float Ks[32][68];
    __shared__ __align__(16) float Vs[32][72];
    __shared__ __align__(16) float Ps[64][36];

    const int tid  = threadIdx.x;
    const int warp = tid >> 5;
    const int lane = tid & 31;
    const int gID  = lane >> 2;
    const int tID  = lane & 3;
    const int qt   = blockIdx.x;
    const int bh   = blockIdx.y;
    const int qbase = qt << 6;
    const int r0   = warp << 4;

    const float sc = 0.125f * 1.44269504088896340736f;  // 1/sqrt(64)*log2(e)

    // Stage Q tile: 64x64, scaled + tf32-rounded (float4 stores).
    {
        const float* qsrc = &g_Q[((size_t)bh * SEQ + qbase) * D_HEAD];
        int row  = tid >> 1;
        int colb = (tid & 1) * 32;
        #pragma unroll
        for (int i = 0; i < 8; i++) {
            float4 v = *reinterpret_cast<const float4*>(
                &qsrc[(size_t)row * 64 + colb + i * 4]);
            v.x *= sc; v.y *= sc; v.z *= sc; v.w *= sc;
            *reinterpret_cast<float4*>(&Qs[row][colb + i * 4]) = f2tf32f4(v);
        }
    }

    float m0 = -1e30f, m1 = -1e30f, l0 = 0.f, l1 = 0.f;
    float co[8][4];
    #pragma unroll
    for (int j = 0; j < 8; j++)
        #pragma unroll
        for (int r = 0; r < 4; r++) co[j][r] = 0.f;

    const float* Kb = &g_K[(size_t)bh * SEQ * D_HEAD];
    const float* Vb = &g_V[(size_t)bh * SEQ * D_HEAD];

    // staging geometry: 4 threads per key row
    const int srow = tid >> 2;
    const int scol = (tid & 3) * 16;

    // prefetch tile 0 into registers
    float4 kf[4], vf[4];
    {
        const float* ks = Kb + (size_t)srow * 64 + scol;
        const float* vs = Vb + (size_t)srow * 64 + scol;
        #pragma unroll
        for (int i = 0; i < 4; i++) {
            kf[i] = *reinterpret_cast<const float4*>(ks + i * 4);
            vf[i] = *reinterpret_cast<const float4*>(vs + i * 4);
        }
    }

    __syncthreads();   // Q visible to all warps

    const int ntiles = 2 * qt + 2;
    for (int t = 0; t < ntiles; t++) {
        // stage prefetched K,V tile (tf32-rounded, float4 stores)
        #pragma unroll
        for (int i = 0; i < 4; i++) {
            *reinterpret_cast<float4*>(&Ks[srow][scol + i * 4]) = f2tf32f4(kf[i]);
            *reinterpret_cast<float4*>(&Vs[srow][scol + i * 4]) = f2tf32f4(vf[i]);
        }
        __syncthreads();

        // prefetch next tile (LDG overlaps compute below)
        if (t + 1 < ntiles) {
            const float* ks = Kb + ((size_t)(t + 1) * 32 + srow) * 64 + scol;
            const float* vs = Vb + ((size_t)(t + 1) * 32 + srow) * 64 + scol;
            #pragma unroll
            for (int i = 0; i < 4; i++) {
                kf[i] = *reinterpret_cast<const float4*>(ks + i * 4);
                vf[i] = *reinterpret_cast<const float4*>(vs + i * 4);
            }
        }

        // ---- S = Q @ K^T  (m16 x n32, k=64) ----
        float sfrag[4][4];
        #pragma unroll
        for (int j = 0; j < 4; j++)
            #pragma unroll
            for (int r = 0; r < 4; r++) sfrag[j][r] = 0.f;

        #pragma unroll
        for (int k8 = 0; k8 < 64; k8 += 8) {
            uint32_t a[4];
            a[0] = __float_as_uint(Qs[r0 + gID    ][k8 + tID    ]);
            a[1] = __float_as_uint(Qs[r0 + gID + 8][k8 + tID    ]);
            a[2] = __float_as_uint(Qs[r0 + gID    ][k8 + tID + 4]);
            a[3] = __float_as_uint(Qs[r0 + gID + 8][k8 + tID + 4]);
            #pragma unroll
            for (int j = 0; j < 4; j++) {
                uint32_t b[2];
                b[0] = __float_as_uint(Ks[j*8 + gID][k8 + tID    ]);
                b[1] = __float_as_uint(Ks[j*8 + gID][k8 + tID + 4]);
                mma_tf32_16x8x8(sfrag[j], a, b);
            }
        }

        // ---- causal mask (only the two diagonal tiles) ----
        const int rg0 = qbase + r0 + gID;
        const int rg1 = rg0 + 8;
        if (t >= 2 * qt) {
            #pragma unroll
            for (int j = 0; j < 4; j++) {
                int key = t * 32 + j * 8 + tID * 2;
                if (key     > rg0) sfrag[j][0] = -1e30f;
                if (key + 1 > rg0) sfrag[j][1] = -1e30f;
                if (key     > rg1) sfrag[j][2] = -1e30f;
                if (key + 1 > rg1) sfrag[j][3] = -1e30f;
            }
        }

        // ---- online softmax ----
        float tm0 = -1e30f, tm1 = -1e30f;
        #pragma unroll
        for (int j = 0; j < 4; j++) {
            tm0 = fmaxf(tm0, fmaxf(sfrag[j][0], sfrag[j][1]));
            tm1 = fmaxf(tm1, fmaxf(sfrag[j][2], sfrag[j][3]));
        }
        tm0 = fmaxf(tm0, __shfl_xor_sync(0xffffffffu, tm0, 1));
        tm0 = fmaxf(tm0, __shfl_xor_sync(0xffffffffu, tm0, 2));
        tm1 = fmaxf(tm1, __shfl_xor_sync(0xffffffffu, tm1, 1));
        tm1 = fmaxf(tm1, __shfl_xor_sync(0xffffffffu, tm1, 2));

        float mn0 = fmaxf(m0, tm0), mn1 = fmaxf(m1, tm1);
        float al0 = exp2f(m0 - mn0), al1 = exp2f(m1 - mn1);
        m0 = mn0; m1 = mn1;

        float ls0 = 0.f, ls1 = 0.f;
        #pragma unroll
        for (int j = 0; j < 4; j++) {
            float p0 = f2tf32f(exp2f(sfrag[j][0] - m0));
            float p1 = f2tf32f(exp2f(sfrag[j][1] - m0));
            float p2 = f2tf32f(exp2f(sfrag[j][2] - m1));
            float p3 = f2tf32f(exp2f(sfrag[j][3] - m1));
            ls0 += p0 + p1;
            ls1 += p2 + p3;
            int col = j * 8 + tID * 2;
            *reinterpret_cast<float2*>(&Ps[r0 + gID    ][col]) = make_float2(p0, p1);
            *reinterpret_cast<float2*>(&Ps[r0 + gID + 8][col]) = make_float2(p2, p3);
        }
        ls0 += __shfl_xor_sync(0xffffffffu, ls0, 1);
        ls0 += __shfl_xor_sync(0xffffffffu, ls0, 2);
        ls1 += __shfl_xor_sync(0xffffffffu, ls1, 1);
        ls1 += __shfl_xor_sync(0xffffffffu, ls1, 2);
        l0 = l0 * al0 + ls0;
        l1 = l1 * al1 + ls1;

        // rescale accumulators
        #pragma unroll
        for (int j = 0; j < 8; j++) {
            co[j][0] *= al0; co[j][1] *= al0;
            co[j][2] *= al1; co[j][3] *= al1;
        }

        __syncwarp();   // P stores visible within warp

        // ---- ctx += P @ V  (m16 x n64, k=32) ----
        #pragma unroll
        for (int k8 = 0; k8 < 32; k8 += 8) {
            uint32_t a[4];
            a[0] = __float_as_uint(Ps[r0 + gID    ][k8 + tID    ]);
            a[1] = __float_as_uint(Ps[r0 + gID + 8][k8 + tID    ]);
            a[2] = __float_as_uint(Ps[r0 + gID    ][k8 + tID + 4]);
            a[3] = __float_as_uint(Ps[r0 + gID + 8][k8 + tID + 4]);
            #pragma unroll
            for (int jn = 0; jn < 8; jn++) {
                uint32_t b[2];
                b[0] = __float_as_uint(Vs[k8 + tID    ][jn*8 + gID]);
                b[1] = __float_as_uint(Vs[k8 + tID + 4][jn*8 + gID]);
                mma_tf32_16x8x8(co[jn], a, b);
            }
        }
        __syncthreads();   // all reads of Ks/Vs done before next stage
    }

    // ---- normalize and write context: [b*s, d_model] ----
    const float inv0 = 1.f / l0;
    const float inv1 = 1.f / l1;
    const int b = bh >> 4;
    const int h = bh & 15;
    const int grow0 = qbase + r0 + gID;
    const int grow1 = grow0 + 8;
    #pragma unroll
    for (int jn = 0; jn < 8; jn++) {
        int col = h * 64 + jn * 8 + tID * 2;
        *reinterpret_cast<float2*>(&g_ctx[(size_t)(b * SEQ + grow0) * D_MODEL + col]) =
            make_float2(co[jn][0] * inv0, co[jn][1] * inv0);
        *reinterpret_cast<float2*>(&g_ctx[(size_t)(b * SEQ + grow1) * D_MODEL + col]) =
            make_float2(co[jn][2] * inv1, co[jn][3] * inv1);
    }
}

// ---------------------------------------------------------------------------
extern "C" void kernel_launch(void* const* d_in, const int* in_sizes, int n_in,
                              void* d_out, int out_size)
{
    const float* x   = (const float*)d_in[0];
    const float* W_q = (const float*)d_in[1];
    const float* b_q = (const float*)d_in[2];
    const float* W_k = (const float*)d_in[3];
    const float* b_k = (const float*)d_in[4];
    const float* W_v = (const float*)d_in[5];
    const float* b_v = (const float*)d_in[6];
    const float* W_o = (const float*)d_in[7];
    const float* b_o = (const float*)d_in[8];
    float* out = (float*)d_out;

    dim3 gProj(M_TOT / 128, D_MODEL / 128, 3);
    qkv_gemm_kernel<<<gProj, 256>>>(x, W_q, b_q, W_k, b_k, W_v, b_v);

    dim3 gAttn(SEQ / 64, BATCH * N_HEADS);
    flash_attn_tc_kernel<<<gAttn, 128>>>();

    dim3 gOut(M_TOT / 128, D_MODEL / 128);
    out_gemm_kernel<<<gOut, 256>>>(W_o, b_o, out);
}

// round 16
// speedup vs baseline: 1.3612x; 1.1303x over previous
#include <cuda_runtime.h>
#include <cstdint>

#define D_MODEL 1024
#define N_HEADS 16
#define D_HEAD  64
#define BATCH   4
#define SEQ     2048
#define M_TOT   (BATCH * SEQ)   // 8192

// Scratch (device globals: allocation-free per harness rules)
__device__ float g_Q[(size_t)BATCH * N_HEADS * SEQ * D_HEAD];   // [b,h,s,dh]
__device__ float g_K[(size_t)BATCH * N_HEADS * SEQ * D_HEAD];
__device__ float g_V[(size_t)BATCH * N_HEADS * SEQ * D_HEAD];
__device__ float g_ctx[(size_t)M_TOT * D_MODEL];                // [b*s, d]

// ---------------------------------------------------------------------------
// tf32 helpers
// ---------------------------------------------------------------------------
__device__ __forceinline__ uint32_t f2tf32(float f) {
    uint32_t u;
    asm("cvt.rna.tf32.f32 %0, %1;" : "=r"(u) : "f"(f));
    return u;
}
__device__ __forceinline__ float f2tf32f(float f) {
    return __uint_as_float(f2tf32(f));
}
__device__ __forceinline__ float4 f2tf32f4(float4 v) {
    return make_float4(f2tf32f(v.x), f2tf32f(v.y), f2tf32f(v.z), f2tf32f(v.w));
}

__device__ __forceinline__ void mma_tf32_16x8x8(
    float c[4], const uint32_t a[4], const uint32_t b[2])
{
    asm volatile(
        "mma.sync.aligned.m16n8k8.row.col.f32.tf32.tf32.f32 "
        "{%0,%1,%2,%3}, {%4,%5,%6,%7}, {%8,%9}, {%0,%1,%2,%3};"
        : "+f"(c[0]), "+f"(c[1]), "+f"(c[2]), "+f"(c[3])
        : "r"(a[0]), "r"(a[1]), "r"(a[2]), "r"(a[3]),
          "r"(b[0]), "r"(b[1]));
}

__device__ __forceinline__ uint32_t smem_u32(const void* p) {
    return (uint32_t)__cvta_generic_to_shared(p);
}

#define CP16(dst_u32, src_ptr) \
    asm volatile("cp.async.cg.shared.global [%0], [%1], 16;" \
                 :: "r"(dst_u32), "l"(src_ptr) : "memory")

// ---------------------------------------------------------------------------
// tf32 tensor-core GEMM core v4 (R15-validated, unchanged):
// 256 threads = 8 warps 2x4, warp tile 64x32, strides 20/136, cp.async
// double-buffered staging, cvt-at-read.
// ---------------------------------------------------------------------------
__device__ __forceinline__ void gemm_tf32_core(
    const float* __restrict__ A,   // [M, 1024] row-major
    const float* __restrict__ W,   // [1024, 1024] row-major
    float acc[4][4][4], int bm, int bn)
{
    __shared__ __align__(16) float As[2][128][20];   // [m][k]
    __shared__ __align__(16) float Bs[2][16][136];   // [k][n]

    const int tid  = threadIdx.x;
    const int warp = tid >> 5;
    const int lane = tid & 31;
    const int gID  = lane >> 2;     // 0..7
    const int tID  = lane & 3;      // 0..3
    const int m_warp = (warp & 1) * 64;
    const int n_warp = (warp >> 1) * 32;

    const int f0 = tid * 2, f1 = f0 + 1;
    const int ar0 = f0 >> 2, ak0 = (f0 & 3) << 2;
    const int ar1 = f1 >> 2, ak1 = (f1 & 3) << 2;
    const int br0 = f0 >> 5, bc0 = (f0 & 31) << 2;
    const int br1 = f1 >> 5, bc1 = (f1 & 31) << 2;

    const float* a0 = A + (size_t)(bm + ar0) * 1024 + ak0;
    const float* a1 = A + (size_t)(bm + ar1) * 1024 + ak1;
    const float* b0 = W + (size_t)br0 * 1024 + bn + bc0;
    const float* b1 = W + (size_t)br1 * 1024 + bn + bc1;

    const uint32_t sa0 = smem_u32(&As[0][ar0][ak0]);
    const uint32_t sa1 = smem_u32(&As[0][ar1][ak1]);
    const uint32_t sb0 = smem_u32(&Bs[0][br0][bc0]);
    const uint32_t sb1 = smem_u32(&Bs[0][br1][bc1]);
    const uint32_t aoff = 128 * 20 * 4;
    const uint32_t boff = 16 * 136 * 4;

    CP16(sa0, a0);
    CP16(sa1, a1);
    CP16(sb0, b0);
    CP16(sb1, b1);
    asm volatile("cp.async.commit_group;" ::: "memory");

    for (int it = 0; it < 64; it++) {
        const int cur = it & 1;

        asm volatile("cp.async.wait_group 0;" ::: "memory");
        __syncthreads();

        if (it + 1 < 64) {
            const uint32_t nb = (uint32_t)(cur ^ 1);
            const int kn = (it + 1) * 16;
            CP16(sa0 + nb * aoff, a0 + kn);
            CP16(sa1 + nb * aoff, a1 + kn);
            CP16(sb0 + nb * boff, b0 + (size_t)kn * 1024);
            CP16(sb1 + nb * boff, b1 + (size_t)kn * 1024);
            asm volatile("cp.async.commit_group;" ::: "memory");
        }

        #pragma unroll
        for (int s = 0; s < 2; s++) {
            const int ks = s * 8;
            uint32_t afrag[4][4];
            #pragma unroll
            for (int i = 0; i < 4; i++) {
                int r = m_warp + i * 16 + gID;
                afrag[i][0] = f2tf32(As[cur][r    ][ks + tID    ]);
                afrag[i][1] = f2tf32(As[cur][r + 8][ks + tID    ]);
                afrag[i][2] = f2tf32(As[cur][r    ][ks + tID + 4]);
                afrag[i][3] = f2tf32(As[cur][r + 8][ks + tID + 4]);
            }
            uint32_t bfrag[4][2];
            #pragma unroll
            for (int j = 0; j < 4; j++) {
                int c = n_warp + j * 8 + gID;
                bfrag[j][0] = f2tf32(Bs[cur][ks + tID    ][c]);
                bfrag[j][1] = f2tf32(Bs[cur][ks + tID + 4][c]);
            }
            #pragma unroll
            for (int i = 0; i < 4; i++)
                #pragma unroll
                for (int j = 0; j < 4; j++)
                    mma_tf32_16x8x8(acc[i][j], afrag[i], bfrag[j]);
        }
    }
}

// ---------------------------------------------------------------------------
// QKV projection (R15 unchanged)
// ---------------------------------------------------------------------------
__global__ __launch_bounds__(256, 2)
void qkv_gemm_kernel(const float* __restrict__ x,
                     const float* __restrict__ Wq, const float* __restrict__ bq,
                     const float* __restrict__ Wk, const float* __restrict__ bk,
                     const float* __restrict__ Wv, const float* __restrict__ bv)
{
    const float* W; const float* bias; float* out;
    if      (blockIdx.z == 0) { W = Wq; bias = bq; out = g_Q; }
    else if (blockIdx.z == 1) { W = Wk; bias = bk; out = g_K; }
    else                      { W = Wv; bias = bv; out = g_V; }

    const int bm = blockIdx.x * 128;
    const int bn = blockIdx.y * 128;

    float acc[4][4][4];
    #pragma unroll
    for (int i = 0; i < 4; i++)
        #pragma unroll
        for (int j = 0; j < 4; j++)
            #pragma unroll
            for (int r = 0; r < 4; r++) acc[i][j][r] = 0.f;

    gemm_tf32_core(x, W, acc, bm, bn);

    const int warp   = threadIdx.x >> 5;
    const int lane   = threadIdx.x & 31;
    const int gID    = lane >> 2;
    const int tID    = lane & 3;
    const int m_warp = (warp & 1) * 64;
    const int n_warp = (warp >> 1) * 32;

    #pragma unroll
    for (int i = 0; i < 4; i++) {
        #pragma unroll
        for (int j = 0; j < 4; j++) {
            int n0 = bn + n_warp + j * 8 + tID * 2;
            int h  = n0 >> 6;
            int dh = n0 & 63;
            float b0v = bias[n0], b1v = bias[n0 + 1];
            #pragma unroll
            for (int rr = 0; rr < 2; rr++) {
                int m = bm + m_warp + i * 16 + gID + rr * 8;
                int b = m >> 11;
                int s = m & (SEQ - 1);
                float* dst = &out[(((size_t)(b * N_HEADS + h) * SEQ + s) * D_HEAD) + dh];
                float2 v = make_float2(acc[i][j][rr * 2] + b0v,
                                       acc[i][j][rr * 2 + 1] + b1v);
                *reinterpret_cast<float2*>(dst) = v;
            }
        }
    }
}

// ---------------------------------------------------------------------------
// Output projection (R15 unchanged)
// ---------------------------------------------------------------------------
__global__ __launch_bounds__(256, 2)
void out_gemm_kernel(const float* __restrict__ Wo,
                     const float* __restrict__ bo,
                     float* __restrict__ out)
{
    const int bm = blockIdx.x * 128;
    const int bn = blockIdx.y * 128;

    float acc[4][4][4];
    #pragma unroll
    for (int i = 0; i < 4; i++)
        #pragma unroll
        for (int j = 0; j < 4; j++)
            #pragma unroll
            for (int r = 0; r < 4; r++) acc[i][j][r] = 0.f;

    gemm_tf32_core(g_ctx, Wo, acc, bm, bn);

    const int warp   = threadIdx.x >> 5;
    const int lane   = threadIdx.x & 31;
    const int gID    = lane >> 2;
    const int tID    = lane & 3;
    const int m_warp = (warp & 1) * 64;
    const int n_warp = (warp >> 1) * 32;

    #pragma unroll
    for (int i = 0; i < 4; i++) {
        #pragma unroll
        for (int j = 0; j < 4; j++) {
            int n0 = bn + n_warp + j * 8 + tID * 2;
            float b0v = bo[n0], b1v = bo[n0 + 1];
            #pragma unroll
            for (int rr = 0; rr < 2; rr++) {
                int m = bm + m_warp + i * 16 + gID + rr * 8;
                float2 v = make_float2(acc[i][j][rr * 2] + b0v,
                                       acc[i][j][rr * 2 + 1] + b1v);
                *reinterpret_cast<float2*>(&out[(size_t)m * D_MODEL + n0]) = v;
            }
        }
    }
}

// ---------------------------------------------------------------------------
// Causal flash attention v2: 128 Q rows per block, 256 threads / 8 warps.
// Warps 0-3 own rows [0,64), warps 4-7 own [64,128) — each staged K/V tile
// serves 2x the Q rows of R15 (staging, cvt, barriers per MMA halved).
// Q fragments live in REGISTERS (loaded once; no Qs smem, no Q LDS in loop).
// Lower warps skip compute (not barriers) past their causal diagonal.
// Heavy blocks launch first. Arithmetic bit-identical to R15.
// grid = (SEQ/128, BATCH*N_HEADS), block = 256.
// ---------------------------------------------------------------------------
__global__ __launch_bounds__(256, 2)
void flash_attn_tc_kernel()
{
    __shared__ __align__(16) float Ks[32][68];   // conflict-free: 4g+t
    __shared__ __align__(16) float Vs[32][72];   // conflict-free: 8t+g
    __shared__ __align__(16) float Ps[128][36];

    const int tid  = threadIdx.x;
    const int warp = tid >> 5;                    // 0..7
    const int lane = tid & 31;
    const int gID  = lane >> 2;
    const int tID  = lane & 3;
    const int qt   = gridDim.x - 1 - blockIdx.x;  // heavy-first
    const int bh   = blockIdx.y;
    const int qbase = qt << 7;                    // 128 rows per block
    const int wrow  = (warp & 3) * 16 + (warp >> 2) * 64;  // warp's row base

    const float sc = 0.125f * 1.44269504088896340736f;  // 1/sqrt(64)*log2(e)

    // ---- Q fragments in registers (one-time gmem load, scaled + tf32) ----
    const int rg0 = qbase + wrow + gID;
    const int rg1 = rg0 + 8;
    uint32_t qf[8][4];
    {
        const float* qp0 = &g_Q[((size_t)bh * SEQ + rg0) * D_HEAD];
        const float* qp1 = qp0 + 8 * D_HEAD;
        #pragma unroll
        for (int s = 0; s < 8; s++) {
            qf[s][0] = f2tf32(qp0[s * 8 + tID    ] * sc);
            qf[s][1] = f2tf32(qp1[s * 8 + tID    ] * sc);
            qf[s][2] = f2tf32(qp0[s * 8 + tID + 4] * sc);
            qf[s][3] = f2tf32(qp1[s * 8 + tID + 4] * sc);
        }
    }

    float m0 = -1e30f, m1 = -1e30f, l0 = 0.f, l1 = 0.f;
    float co[8][4];
    #pragma unroll
    for (int j = 0; j < 8; j++)
        #pragma unroll
        for (int r = 0; r < 4; r++) co[j][r] = 0.f;

    const float* Kb = &g_K[(size_t)bh * SEQ * D_HEAD];
    const float* Vb = &g_V[(size_t)bh * SEQ * D_HEAD];

    // staging: 8 threads per key row, 8 floats each
    const int srow = tid >> 3;          // 0..31
    const int scol = (tid & 7) * 8;     // 0..56

    // prefetch tile 0
    float4 kf[2], vf[2];
    {
        const float* ks = Kb + (size_t)srow * 64 + scol;
        const float* vs = Vb + (size_t)srow * 64 + scol;
        kf[0] = *reinterpret_cast<const float4*>(ks);
        kf[1] = *reinterpret_cast<const float4*>(ks + 4);
        vf[0] = *reinterpret_cast<const float4*>(vs);
        vf[1] = *reinterpret_cast<const float4*>(vs + 4);
    }

    const int ntiles    = 4 * qt + 4;
    const int last_t    = (qbase + wrow + 15) >> 5;   // warp's final tile
    const int mask_from = (qbase + wrow) >> 5;        // first tile needing mask

    for (int t = 0; t < ntiles; t++) {
        // ---- stage prefetched K/V (tf32-rounded) ----
        *reinterpret_cast<float4*>(&Ks[srow][scol    ]) = f2tf32f4(kf[0]);
        *reinterpret_cast<float4*>(&Ks[srow][scol + 4]) = f2tf32f4(kf[1]);
        *reinterpret_cast<float4*>(&Vs[srow][scol    ]) = f2tf32f4(vf[0]);
        *reinterpret_cast<float4*>(&Vs[srow][scol + 4]) = f2tf32f4(vf[1]);
        __syncthreads();

        // prefetch next tile (overlaps compute)
        if (t + 1 < ntiles) {
            const float* ks = Kb + ((size_t)(t + 1) * 32 + srow) * 64 + scol;
            const float* vs = Vb + ((size_t)(t + 1) * 32 + srow) * 64 + scol;
            kf[0] = *reinterpret_cast<const float4*>(ks);
            kf[1] = *reinterpret_cast<const float4*>(ks + 4);
            vf[0] = *reinterpret_cast<const float4*>(vs);
            vf[1] = *reinterpret_cast<const float4*>(vs + 4);
        }

        if (t <= last_t) {   // warp-uniform: skip compute past causal diagonal
            // ---- S = Q @ K^T  (m16 x n32, k=64), Q from registers ----
            float sfrag[4][4];
            #pragma unroll
            for (int j = 0; j < 4; j++)
                #pragma unroll
                for (int r = 0; r < 4; r++) sfrag[j][r] = 0.f;

            #pragma unroll
            for (int s = 0; s < 8; s++) {
                const int k8 = s * 8;
                #pragma unroll
                for (int j = 0; j < 4; j++) {
                    uint32_t b[2];
                    b[0] = __float_as_uint(Ks[j*8 + gID][k8 + tID    ]);
                    b[1] = __float_as_uint(Ks[j*8 + gID][k8 + tID + 4]);
                    mma_tf32_16x8x8(sfrag[j], qf[s], b);
                }
            }

            // ---- causal mask ----
            if (t >= mask_from) {
                #pragma unroll
                for (int j = 0; j < 4; j++) {
                    int key = t * 32 + j * 8 + tID * 2;
                    if (key     > rg0) sfrag[j][0] = -1e30f;
                    if (key + 1 > rg0) sfrag[j][1] = -1e30f;
                    if (key     > rg1) sfrag[j][2] = -1e30f;
                    if (key + 1 > rg1) sfrag[j][3] = -1e30f;
                }
            }

            // ---- online softmax ----
            float tm0 = -1e30f, tm1 = -1e30f;
            #pragma unroll
            for (int j = 0; j < 4; j++) {
                tm0 = fmaxf(tm0, fmaxf(sfrag[j][0], sfrag[j][1]));
                tm1 = fmaxf(tm1, fmaxf(sfrag[j][2], sfrag[j][3]));
            }
            tm0 = fmaxf(tm0, __shfl_xor_sync(0xffffffffu, tm0, 1));
            tm0 = fmaxf(tm0, __shfl_xor_sync(0xffffffffu, tm0, 2));
            tm1 = fmaxf(tm1, __shfl_xor_sync(0xffffffffu, tm1, 1));
            tm1 = fmaxf(tm1, __shfl_xor_sync(0xffffffffu, tm1, 2));

            float mn0 = fmaxf(m0, tm0), mn1 = fmaxf(m1, tm1);
            float al0 = exp2f(m0 - mn0), al1 = exp2f(m1 - mn1);
            m0 = mn0; m1 = mn1;

            float ls0 = 0.f, ls1 = 0.f;
            #pragma unroll
            for (int j = 0; j < 4; j++) {
                float p0 = f2tf32f(exp2f(sfrag[j][0] - m0));
                float p1 = f2tf32f(exp2f(sfrag[j][1] - m0));
                float p2 = f2tf32f(exp2f(sfrag[j][2] - m1));
                float p3 = f2tf32f(exp2f(sfrag[j][3] - m1));
                ls0 += p0 + p1;
                ls1 += p2 + p3;
                int col = j * 8 + tID * 2;
                *reinterpret_cast<float2*>(&Ps[wrow + gID    ][col]) = make_float2(p0, p1);
                *reinterpret_cast<float2*>(&Ps[wrow + gID + 8][col]) = make_float2(p2, p3);
            }
            ls0 += __shfl_xor_sync(0xffffffffu, ls0, 1);
            ls0 += __shfl_xor_sync(0xffffffffu, ls0, 2);
            ls1 += __shfl_xor_sync(0xffffffffu, ls1, 1);
            ls1 += __shfl_xor_sync(0xffffffffu, ls1, 2);
            l0 = l0 * al0 + ls0;
            l1 = l1 * al1 + ls1;

            #pragma unroll
            for (int j = 0; j < 8; j++) {
                co[j][0] *= al0; co[j][1] *= al0;
                co[j][2] *= al1; co[j][3] *= al1;
            }

            __syncwarp();   // P stores visible within warp

            // ---- ctx += P @ V  (m16 x n64, k=32) ----
            #pragma unroll
            for (int k8 = 0; k8 < 32; k8 += 8) {
                uint32_t a[4];
                a[0] = __float_as_uint(Ps[wrow + gID    ][k8 + tID    ]);
                a[1] = __float_as_uint(Ps[wrow + gID + 8][k8 + tID    ]);
                a[2] = __float_as_uint(Ps[wrow + gID    ][k8 + tID + 4]);
                a[3] = __float_as_uint(Ps[wrow + gID + 8][k8 + tID + 4]);
                #pragma unroll
                for (int jn = 0; jn < 8; jn++) {
                    uint32_t b[2];
                    b[0] = __float_as_uint(Vs[k8 + tID    ][jn*8 + gID]);
                    b[1] = __float_as_uint(Vs[k8 + tID + 4][jn*8 + gID]);
                    mma_tf32_16x8x8(co[jn], a, b);
                }
            }
        }
        __syncthreads();   // all reads of Ks/Vs done before next stage
    }

    // ---- normalize and write context: [b*s, d_model] ----
    const float inv0 = 1.f / l0;
    const float inv1 = 1.f / l1;
    const int b = bh >> 4;
    const int h = bh & 15;
    #pragma unroll
    for (int jn = 0; jn < 8; jn++) {
        int col = h * 64 + jn * 8 + tID * 2;
        *reinterpret_cast<float2*>(&g_ctx[(size_t)(b * SEQ + rg0) * D_MODEL + col]) =
            make_float2(co[jn][0] * inv0, co[jn][1] * inv0);
        *reinterpret_cast<float2*>(&g_ctx[(size_t)(b * SEQ + rg1) * D_MODEL + col]) =
            make_float2(co[jn][2] * inv1, co[jn][3] * inv1);
    }
}

// ---------------------------------------------------------------------------
extern "C" void kernel_launch(void* const* d_in, const int* in_sizes, int n_in,
                              void* d_out, int out_size)
{
    const float* x   = (const float*)d_in[0];
    const float* W_q = (const float*)d_in[1];
    const float* b_q = (const float*)d_in[2];
    const float* W_k = (const float*)d_in[3];
    const float* b_k = (const float*)d_in[4];
    const float* W_v = (const float*)d_in[5];
    const float* b_v = (const float*)d_in[6];
    const float* W_o = (const float*)d_in[7];
    const float* b_o = (const float*)d_in[8];
    float* out = (float*)d_out;

    dim3 gProj(M_TOT / 128, D_MODEL / 128, 3);
    qkv_gemm_kernel<<<gProj, 256>>>(x, W_q, b_q, W_k, b_k, W_v, b_v);

    dim3 gAttn(SEQ / 128, BATCH * N_HEADS);
    flash_attn_tc_kernel<<<gAttn, 256>>>();

    dim3 gOut(M_TOT / 128, D_MODEL / 128);
    out_gemm_kernel<<<gOut, 256>>>(W_o, b_o, out);
}

// round 17
// speedup vs baseline: 2.0803x; 1.5282x over previous
#include <cuda_runtime.h>
#include <cuda_fp16.h>
#include <cstdint>

#define D_MODEL 1024
#define N_HEADS 16
#define D_HEAD  64
#define BATCH   4
#define SEQ     2048
#define M_TOT   (BATCH * SEQ)   // 8192

// Scratch (device globals: allocation-free per harness rules)
__device__ float  g_Q[(size_t)BATCH * N_HEADS * SEQ * D_HEAD];   // [b,h,s,dh]
__device__ float  g_K[(size_t)BATCH * N_HEADS * SEQ * D_HEAD];
__device__ float  g_V[(size_t)BATCH * N_HEADS * SEQ * D_HEAD];
__device__ __half g_xh[(size_t)M_TOT * D_MODEL];                 // x in fp16
__device__ __half g_Wh[4][(size_t)D_MODEL * D_MODEL];            // Wq,Wk,Wv,Wo fp16
__device__ __half g_ctxh[(size_t)M_TOT * D_MODEL];               // ctx fp16

// ---------------------------------------------------------------------------
// helpers
// ---------------------------------------------------------------------------
__device__ __forceinline__ uint32_t f2tf32(float f) {
    uint32_t u;
    asm("cvt.rna.tf32.f32 %0, %1;" : "=r"(u) : "f"(f));
    return u;
}
__device__ __forceinline__ float f2tf32f(float f) {
    return __uint_as_float(f2tf32(f));
}
__device__ __forceinline__ float4 f2tf32f4(float4 v) {
    return make_float4(f2tf32f(v.x), f2tf32f(v.y), f2tf32f(v.z), f2tf32f(v.w));
}

__device__ __forceinline__ void mma_tf32_16x8x8(
    float c[4], const uint32_t a[4], const uint32_t b[2])
{
    asm volatile(
        "mma.sync.aligned.m16n8k8.row.col.f32.tf32.tf32.f32 "
        "{%0,%1,%2,%3}, {%4,%5,%6,%7}, {%8,%9}, {%0,%1,%2,%3};"
        : "+f"(c[0]), "+f"(c[1]), "+f"(c[2]), "+f"(c[3])
        : "r"(a[0]), "r"(a[1]), "r"(a[2]), "r"(a[3]),
          "r"(b[0]), "r"(b[1]));
}

__device__ __forceinline__ void mma_f16_16x8x16(
    float c[4], const uint32_t a[4], const uint32_t b[2])
{
    asm volatile(
        "mma.sync.aligned.m16n8k16.row.col.f32.f16.f16.f32 "
        "{%0,%1,%2,%3}, {%4,%5,%6,%7}, {%8,%9}, {%0,%1,%2,%3};"
        : "+f"(c[0]), "+f"(c[1]), "+f"(c[2]), "+f"(c[3])
        : "r"(a[0]), "r"(a[1]), "r"(a[2]), "r"(a[3]),
          "r"(b[0]), "r"(b[1]));
}

__device__ __forceinline__ void ldsm_x4(uint32_t r[4], uint32_t addr) {
    asm volatile("ldmatrix.sync.aligned.m8n8.x4.shared.b16 {%0,%1,%2,%3}, [%4];"
                 : "=r"(r[0]), "=r"(r[1]), "=r"(r[2]), "=r"(r[3]) : "r"(addr));
}
__device__ __forceinline__ void ldsm_x4_t(uint32_t r[4], uint32_t addr) {
    asm volatile("ldmatrix.sync.aligned.m8n8.x4.trans.shared.b16 {%0,%1,%2,%3}, [%4];"
                 : "=r"(r[0]), "=r"(r[1]), "=r"(r[2]), "=r"(r[3]) : "r"(addr));
}

__device__ __forceinline__ uint32_t smem_u32(const void* p) {
    return (uint32_t)__cvta_generic_to_shared(p);
}

#define CP16(dst_u32, src_ptr) \
    asm volatile("cp.async.cg.shared.global [%0], [%1], 16;" \
                 :: "r"(dst_u32), "l"(src_ptr) : "memory")

// ---------------------------------------------------------------------------
// fp32 -> fp16 convert pre-pass (sel 0 = x, 1..4 = Wq,Wk,Wv,Wo)
// ---------------------------------------------------------------------------
__global__ void f2h_kernel(const float* __restrict__ src, int sel, int n4)
{
    int i = blockIdx.x * blockDim.x + threadIdx.x;
    if (i >= n4) return;
    __half* dst = (sel == 0) ? g_xh : g_Wh[sel - 1];
    float4 v = reinterpret_cast<const float4*>(src)[i];
    __half2* d = reinterpret_cast<__half2*>(dst) + i * 2;
    d[0] = __floats2half2_rn(v.x, v.y);
    d[1] = __floats2half2_rn(v.z, v.w);
}

// ---------------------------------------------------------------------------
// fp16 tensor-core GEMM core: C_tile(128x128) = A(128xK) * W(Kx128), K=1024.
// 256 threads = 8 warps 2(M) x 4(N), warp tile 64x32 via 4x4 m16n8k16.
// k-tile = 32. cp.async double-buffered raw-fp16 staging; fragments via
// ldmatrix (A: x4, B: x4.trans). Strides: A 40 halves (80B -> banks 20r,
// permutation), B 136 halves (272B -> 4r, permutation): conflict-free.
// ---------------------------------------------------------------------------
__device__ __forceinline__ void gemm_f16_core(
    const __half* __restrict__ A,   // [M, 1024] row-major halves
    const __half* __restrict__ W,   // [1024, 1024] row-major halves
    float acc[4][4][4], int bm, int bn)
{
    __shared__ __align__(16) __half Ash[2][128][40];
    __shared__ __align__(16) __half Bsh[2][32][136];

    const int tid  = threadIdx.x;
    const int warp = tid >> 5;
    const int lane = tid & 31;
    const int m_warp = (warp & 1) * 64;
    const int n_warp = (warp >> 1) * 32;

    // staging: 512 16B-chunks per tile for each of A and B; 2 per thread
    const int c0 = tid * 2, c1 = c0 + 1;
    const int ar0 = c0 >> 2, ak0 = (c0 & 3) * 8;
    const int ar1 = c1 >> 2, ak1 = (c1 & 3) * 8;
    const int bk0 = c0 >> 4, bn0 = (c0 & 15) * 8;
    const int bk1 = c1 >> 4, bn1 = (c1 & 15) * 8;

    const __half* aS0 = A + (size_t)(bm + ar0) * 1024 + ak0;
    const __half* aS1 = A + (size_t)(bm + ar1) * 1024 + ak1;
    const __half* bS0 = W + (size_t)bk0 * 1024 + bn + bn0;
    const __half* bS1 = W + (size_t)bk1 * 1024 + bn + bn1;

    const uint32_t sa0 = smem_u32(&Ash[0][ar0][ak0]);
    const uint32_t sa1 = smem_u32(&Ash[0][ar1][ak1]);
    const uint32_t sb0 = smem_u32(&Bsh[0][bk0][bn0]);
    const uint32_t sb1 = smem_u32(&Bsh[0][bk1][bn1]);
    const uint32_t ABUF = 128 * 40 * 2;   // bytes per A buffer
    const uint32_t BBUF = 32 * 136 * 2;   // bytes per B buffer

    // fragment base addresses (buffer 0, s = 0)
    const int seg = lane >> 3, rr = lane & 7;
    const int afrow = (seg & 1) * 8 + rr;
    const int afcol = (seg >> 1) * 8;
    uint32_t aF[4], bF[2];
    #pragma unroll
    for (int mi = 0; mi < 4; mi++)
        aF[mi] = smem_u32(&Ash[0][m_warp + mi * 16 + afrow][afcol]);
    bF[0] = smem_u32(&Bsh[0][afrow][n_warp + afcol]);
    bF[1] = smem_u32(&Bsh[0][afrow][n_warp + 16 + afcol]);

    // prologue: stage k-tile 0 into buffer 0
    CP16(sa0, aS0);
    CP16(sa1, aS1);
    CP16(sb0, bS0);
    CP16(sb1, bS1);
    asm volatile("cp.async.commit_group;" ::: "memory");

    for (int it = 0; it < 32; it++) {
        const int cur = it & 1;
        const uint32_t aOff = cur ? ABUF : 0;
        const uint32_t bOff = cur ? BBUF : 0;

        asm volatile("cp.async.wait_group 0;" ::: "memory");
        __syncthreads();

        if (it + 1 < 32) {
            const uint32_t na = (cur ^ 1) ? ABUF : 0;
            const uint32_t nb = (cur ^ 1) ? BBUF : 0;
            const int kn = (it + 1) * 32;
            CP16(sa0 + na, aS0 + kn);
            CP16(sa1 + na, aS1 + kn);
            CP16(sb0 + nb, bS0 + (size_t)kn * 1024);
            CP16(sb1 + nb, bS1 + (size_t)kn * 1024);
            asm volatile("cp.async.commit_group;" ::: "memory");
        }

        #pragma unroll
        for (int s = 0; s < 2; s++) {
            uint32_t a[4][4], b[4][2];
            #pragma unroll
            for (int mi = 0; mi < 4; mi++)
                ldsm_x4(a[mi], aF[mi] + aOff + s * 32);          // +16 halves
            {
                uint32_t t0[4], t1[4];
                ldsm_x4_t(t0, bF[0] + bOff + s * 16 * 136 * 2);  // +16 k-rows
                ldsm_x4_t(t1, bF[1] + bOff + s * 16 * 136 * 2);
                b[0][0] = t0[0]; b[0][1] = t0[1];
                b[1][0] = t0[2]; b[1][1] = t0[3];
                b[2][0] = t1[0]; b[2][1] = t1[1];
                b[3][0] = t1[2]; b[3][1] = t1[3];
            }
            #pragma unroll
            for (int mi = 0; mi < 4; mi++)
                #pragma unroll
                for (int nj = 0; nj < 4; nj++)
                    mma_f16_16x8x16(acc[mi][nj], a[mi], b[nj]);
        }
    }
}

// ---------------------------------------------------------------------------
// QKV projection: out = x @ W_{q,k,v} + b, written in [b,h,s,dh] fp32 layout.
// grid = (M/128, N/128, 3), z selects Q/K/V.
// ---------------------------------------------------------------------------
__global__ __launch_bounds__(256, 2)
void qkv_gemm_kernel(const float* __restrict__ bq,
                     const float* __restrict__ bk,
                     const float* __restrict__ bv)
{
    const __half* W = g_Wh[blockIdx.z];
    const float* bias; float* out;
    if      (blockIdx.z == 0) { bias = bq; out = g_Q; }
    else if (blockIdx.z == 1) { bias = bk; out = g_K; }
    else                      { bias = bv; out = g_V; }

    const int bm = blockIdx.x * 128;
    const int bn = blockIdx.y * 128;

    float acc[4][4][4];
    #pragma unroll
    for (int i = 0; i < 4; i++)
        #pragma unroll
        for (int j = 0; j < 4; j++)
            #pragma unroll
            for (int r = 0; r < 4; r++) acc[i][j][r] = 0.f;

    gemm_f16_core(g_xh, W, acc, bm, bn);

    const int warp   = threadIdx.x >> 5;
    const int lane   = threadIdx.x & 31;
    const int gID    = lane >> 2;
    const int tID    = lane & 3;
    const int m_warp = (warp & 1) * 64;
    const int n_warp = (warp >> 1) * 32;

    #pragma unroll
    for (int i = 0; i < 4; i++) {
        #pragma unroll
        for (int j = 0; j < 4; j++) {
            int n0 = bn + n_warp + j * 8 + tID * 2;
            int h  = n0 >> 6;
            int dh = n0 & 63;
            float b0v = bias[n0], b1v = bias[n0 + 1];
            #pragma unroll
            for (int rr = 0; rr < 2; rr++) {
                int m = bm + m_warp + i * 16 + gID + rr * 8;
                int b = m >> 11;
                int s = m & (SEQ - 1);
                float* dst = &out[(((size_t)(b * N_HEADS + h) * SEQ + s) * D_HEAD) + dh];
                float2 v = make_float2(acc[i][j][rr * 2] + b0v,
                                       acc[i][j][rr * 2 + 1] + b1v);
                *reinterpret_cast<float2*>(dst) = v;
            }
        }
    }
}

// ---------------------------------------------------------------------------
// Output projection: out = ctx_h @ W_o + b_o   (fp32 output)
// ---------------------------------------------------------------------------
__global__ __launch_bounds__(256, 2)
void out_gemm_kernel(const float* __restrict__ bo,
                     float* __restrict__ out)
{
    const int bm = blockIdx.x * 128;
    const int bn = blockIdx.y * 128;

    float acc[4][4][4];
    #pragma unroll
    for (int i = 0; i < 4; i++)
        #pragma unroll
        for (int j = 0; j < 4; j++)
            #pragma unroll
            for (int r = 0; r < 4; r++) acc[i][j][r] = 0.f;

    gemm_f16_core(g_ctxh, g_Wh[3], acc, bm, bn);

    const int warp   = threadIdx.x >> 5;
    const int lane   = threadIdx.x & 31;
    const int gID    = lane >> 2;
    const int tID    = lane & 3;
    const int m_warp = (warp & 1) * 64;
    const int n_warp = (warp >> 1) * 32;

    #pragma unroll
    for (int i = 0; i < 4; i++) {
        #pragma unroll
        for (int j = 0; j < 4; j++) {
            int n0 = bn + n_warp + j * 8 + tID * 2;
            float b0v = bo[n0], b1v = bo[n0 + 1];
            #pragma unroll
            for (int rr = 0; rr < 2; rr++) {
                int m = bm + m_warp + i * 16 + gID + rr * 8;
                float2 v = make_float2(acc[i][j][rr * 2] + b0v,
                                       acc[i][j][rr * 2 + 1] + b1v);
                *reinterpret_cast<float2*>(&out[(size_t)m * D_MODEL + n0]) = v;
            }
        }
    }
}

// ---------------------------------------------------------------------------
// Causal flash attention (R16-validated, tf32). Only change: ctx written as
// fp16 (it would be rounded to 11-bit at out_gemm ingest anyway).
// grid = (SEQ/128, BATCH*N_HEADS), block = 256.
// ---------------------------------------------------------------------------
__global__ __launch_bounds__(256, 2)
void flash_attn_tc_kernel()
{
    __shared__ __align__(16) float Ks[32][68];
    __shared__ __align__(16) float Vs[32][72];
    __shared__ __align__(16) float Ps[128][36];

    const int tid  = threadIdx.x;
    const int warp = tid >> 5;
    const int lane = tid & 31;
    const int gID  = lane >> 2;
    const int tID  = lane & 3;
    const int qt   = gridDim.x - 1 - blockIdx.x;
    const int bh   = blockIdx.y;
    const int qbase = qt << 7;
    const int wrow  = (warp & 3) * 16 + (warp >> 2) * 64;

    const float sc = 0.125f * 1.44269504088896340736f;

    const int rg0 = qbase + wrow + gID;
    const int rg1 = rg0 + 8;
    uint32_t qf[8][4];
    {
        const float* qp0 = &g_Q[((size_t)bh * SEQ + rg0) * D_HEAD];
        const float* qp1 = qp0 + 8 * D_HEAD;
        #pragma unroll
        for (int s = 0; s < 8; s++) {
            qf[s][0] = f2tf32(qp0[s * 8 + tID    ] * sc);
            qf[s][1] = f2tf32(qp1[s * 8 + tID    ] * sc);
            qf[s][2] = f2tf32(qp0[s * 8 + tID + 4] * sc);
            qf[s][3] = f2tf32(qp1[s * 8 + tID + 4] * sc);
        }
    }

    float m0 = -1e30f, m1 = -1e30f, l0 = 0.f, l1 = 0.f;
    float co[8][4];
    #pragma unroll
    for (int j = 0; j < 8; j++)
        #pragma unroll
        for (int r = 0; r < 4; r++) co[j][r] = 0.f;

    const float* Kb = &g_K[(size_t)bh * SEQ * D_HEAD];
    const float* Vb = &g_V[(size_t)bh * SEQ * D_HEAD];

    const int srow = tid >> 3;
    const int scol = (tid & 7) * 8;

    float4 kf[2], vf[2];
    {
        const float* ks = Kb + (size_t)srow * 64 + scol;
        const float* vs = Vb + (size_t)srow * 64 + scol;
        kf[0] = *reinterpret_cast<const float4*>(ks);
        kf[1] = *reinterpret_cast<const float4*>(ks + 4);
        vf[0] = *reinterpret_cast<const float4*>(vs);
        vf[1] = *reinterpret_cast<const float4*>(vs + 4);
    }

    const int ntiles    = 4 * qt + 4;
    const int last_t    = (qbase + wrow + 15) >> 5;
    const int mask_from = (qbase + wrow) >> 5;

    for (int t = 0; t < ntiles; t++) {
        *reinterpret_cast<float4*>(&Ks[srow][scol    ]) = f2tf32f4(kf[0]);
        *reinterpret_cast<float4*>(&Ks[srow][scol + 4]) = f2tf32f4(kf[1]);
        *reinterpret_cast<float4*>(&Vs[srow][scol    ]) = f2tf32f4(vf[0]);
        *reinterpret_cast<float4*>(&Vs[srow][scol + 4]) = f2tf32f4(vf[1]);
        __syncthreads();

        if (t + 1 < ntiles) {
            const float* ks = Kb + ((size_t)(t + 1) * 32 + srow) * 64 + scol;
            const float* vs = Vb + ((size_t)(t + 1) * 32 + srow) * 64 + scol;
            kf[0] = *reinterpret_cast<const float4*>(ks);
            kf[1] = *reinterpret_cast<const float4*>(ks + 4);
            vf[0] = *reinterpret_cast<const float4*>(vs);
            vf[1] = *reinterpret_cast<const float4*>(vs + 4);
        }

        if (t <= last_t) {
            float sfrag[4][4];
            #pragma unroll
            for (int j = 0; j < 4; j++)
                #pragma unroll
                for (int r = 0; r < 4; r++) sfrag[j][r] = 0.f;

            #pragma unroll
            for (int s = 0; s < 8; s++) {
                const int k8 = s * 8;
                #pragma unroll
                for (int j = 0; j < 4; j++) {
                    uint32_t b[2];
                    b[0] = __float_as_uint(Ks[j*8 + gID][k8 + tID    ]);
                    b[1] = __float_as_uint(Ks[j*8 + gID][k8 + tID + 4]);
                    mma_tf32_16x8x8(sfrag[j], qf[s], b);
                }
            }

            if (t >= mask_from) {
                #pragma unroll
                for (int j = 0; j < 4; j++) {
                    int key = t * 32 + j * 8 + tID * 2;
                    if (key     > rg0) sfrag[j][0] = -1e30f;
                    if (key + 1 > rg0) sfrag[j][1] = -1e30f;
                    if (key     > rg1) sfrag[j][2] = -1e30f;
                    if (key + 1 > rg1) sfrag[j][3] = -1e30f;
                }
            }

            float tm0 = -1e30f, tm1 = -1e30f;
            #pragma unroll
            for (int j = 0; j < 4; j++) {
                tm0 = fmaxf(tm0, fmaxf(sfrag[j][0], sfrag[j][1]));
                tm1 = fmaxf(tm1, fmaxf(sfrag[j][2], sfrag[j][3]));
            }
            tm0 = fmaxf(tm0, __shfl_xor_sync(0xffffffffu, tm0, 1));
            tm0 = fmaxf(tm0, __shfl_xor_sync(0xffffffffu, tm0, 2));
            tm1 = fmaxf(tm1, __shfl_xor_sync(0xffffffffu, tm1, 1));
            tm1 = fmaxf(tm1, __shfl_xor_sync(0xffffffffu, tm1, 2));

            float mn0 = fmaxf(m0, tm0), mn1 = fmaxf(m1, tm1);
            float al0 = exp2f(m0 - mn0), al1 = exp2f(m1 - mn1);
            m0 = mn0; m1 = mn1;

            float ls0 = 0.f, ls1 = 0.f;
            #pragma unroll
            for (int j = 0; j < 4; j++) {
                float p0 = f2tf32f(exp2f(sfrag[j][0] - m0));
                float p1 = f2tf32f(exp2f(sfrag[j][1] - m0));
                float p2 = f2tf32f(exp2f(sfrag[j][2] - m1));
                float p3 = f2tf32f(exp2f(sfrag[j][3] - m1));
                ls0 += p0 + p1;
                ls1 += p2 + p3;
                int col = j * 8 + tID * 2;
                *reinterpret_cast<float2*>(&Ps[wrow + gID    ][col]) = make_float2(p0, p1);
                *reinterpret_cast<float2*>(&Ps[wrow + gID + 8][col]) = make_float2(p2, p3);
            }
            ls0 += __shfl_xor_sync(0xffffffffu, ls0, 1);
            ls0 += __shfl_xor_sync(0xffffffffu, ls0, 2);
            ls1 += __shfl_xor_sync(0xffffffffu, ls1, 1);
            ls1 += __shfl_xor_sync(0xffffffffu, ls1, 2);
            l0 = l0 * al0 + ls0;
            l1 = l1 * al1 + ls1;

            #pragma unroll
            for (int j = 0; j < 8; j++) {
                co[j][0] *= al0; co[j][1] *= al0;
                co[j][2] *= al1; co[j][3] *= al1;
            }

            __syncwarp();

            #pragma unroll
            for (int k8 = 0; k8 < 32; k8 += 8) {
                uint32_t a[4];
                a[0] = __float_as_uint(Ps[wrow + gID    ][k8 + tID    ]);
                a[1] = __float_as_uint(Ps[wrow + gID + 8][k8 + tID    ]);
                a[2] = __float_as_uint(Ps[wrow + gID    ][k8 + tID + 4]);
                a[3] = __float_as_uint(Ps[wrow + gID + 8][k8 + tID + 4]);
                #pragma unroll
                for (int jn = 0; jn < 8; jn++) {
                    uint32_t b[2];
                    b[0] = __float_as_uint(Vs[k8 + tID    ][jn*8 + gID]);
                    b[1] = __float_as_uint(Vs[k8 + tID + 4][jn*8 + gID]);
                    mma_tf32_16x8x8(co[jn], a, b);
                }
            }
        }
        __syncthreads();
    }

    // ---- normalize and write context as fp16: [b*s, d_model] ----
    const float inv0 = 1.f / l0;
    const float inv1 = 1.f / l1;
    const int b = bh >> 4;
    const int h = bh & 15;
    #pragma unroll
    for (int jn = 0; jn < 8; jn++) {
        int col = h * 64 + jn * 8 + tID * 2;
        *reinterpret_cast<__half2*>(&g_ctxh[(size_t)(b * SEQ + rg0) * D_MODEL + col]) =
            __floats2half2_rn(co[jn][0] * inv0, co[jn][1] * inv0);
        *reinterpret_cast<__half2*>(&g_ctxh[(size_t)(b * SEQ + rg1) * D_MODEL + col]) =
            __floats2half2_rn(co[jn][2] * inv1, co[jn][3] * inv1);
    }
}

// ---------------------------------------------------------------------------
extern "C" void kernel_launch(void* const* d_in, const int* in_sizes, int n_in,
                              void* d_out, int out_size)
{
    const float* x   = (const float*)d_in[0];
    const float* W_q = (const float*)d_in[1];
    const float* b_q = (const float*)d_in[2];
    const float* W_k = (const float*)d_in[3];
    const float* b_k = (const float*)d_in[4];
    const float* W_v = (const float*)d_in[5];
    const float* b_v = (const float*)d_in[6];
    const float* W_o = (const float*)d_in[7];
    const float* b_o = (const float*)d_in[8];
    float* out = (float*)d_out;

    // fp32 -> fp16 pre-pass (x + 4 weight matrices)
    const int nx4 = M_TOT * D_MODEL / 4;
    const int nw4 = D_MODEL * D_MODEL / 4;
    f2h_kernel<<<(nx4 + 255) / 256, 256>>>(x,   0, nx4);
    f2h_kernel<<<(nw4 + 255) / 256, 256>>>(W_q, 1, nw4);
    f2h_kernel<<<(nw4 + 255) / 256, 256>>>(W_k, 2, nw4);
    f2h_kernel<<<(nw4 + 255) / 256, 256>>>(W_v, 3, nw4);
    f2h_kernel<<<(nw4 + 255) / 256, 256>>>(W_o, 4, nw4);

    dim3 gProj(M_TOT / 128, D_MODEL / 128, 3);
    qkv_gemm_kernel<<<gProj, 256>>>(b_q, b_k, b_v);

    dim3 gAttn(SEQ / 128, BATCH * N_HEADS);
    flash_attn_tc_kernel<<<gAttn, 256>>>();

    dim3 gOut(M_TOT / 128, D_MODEL / 128);
    out_gemm_kernel<<<gOut, 256>>>(b_o, out);
}